// round 16
// baseline (speedup 1.0000x reference)
#include <cuda_runtime.h>
#include <cuda_bf16.h>

// CausalSequenceCML: 16 fused steps of depthwise-causal-conv logistic CML.
// B=4, T=4096, C=512, K=4, STEPS=16.
//
// Round-16: R15 (43.4us, 92% of the mixed-rt FFMA floor) with hot-loop
// address overhead removed:
//  - step loop unrolled x2 with EXPLICIT ping-pong buffers (bm0 -> bm1,
//    bm1 -> bm0): the step&1 select and exchange-address recompute vanish;
//    both smem base offsets become compile-time constants.
//  - __ldg on the 7 read-only parameter loads.
//  - geometry/math identical to R15 (CC=8 x SS=40 x LL=14, TILE=560,
//    VALID=512, NTILES=8 exact; 5 FMA/cell, tails reused, phantom zero
//    strip). rel_err must be bit-identical (2.420138e-6).

#define Bdim 4
#define Tdim 4096
#define Cdim 512
#define NSTEPS 16
#define CC 8                 // channels per block (thread c = tid&7)
#define SS 40                // time strips per block
#define LL 14                // cells per thread
#define TILE (SS * LL)       // 560
#define HALO 48              // 3 * NSTEPS
#define VALID (TILE - HALO)  // 512
#define NTILES (Tdim / VALID) // 8, exact

__global__ void __launch_bounds__(CC * SS, 3)
cml_kernel(const float* __restrict__ drive,
           const float* __restrict__ r,
           const float* __restrict__ eps,
           const float* __restrict__ beta,
           const float* __restrict__ Kc,
           float* __restrict__ out)
{
    // two explicit boundary buffers, phantom zero strip at index 0
    __shared__ float bm0[SS + 1][3][CC];
    __shared__ float bm1[SS + 1][3][CC];

    const int tid = threadIdx.x;
    const int c   = tid & (CC - 1);
    const int s   = tid / CC;
    const int cg  = blockIdx.y * CC + c;
    const int b   = blockIdx.z;
    const int gt0 = (int)blockIdx.x * VALID - HALO;
    const int base = b * (Tdim * Cdim);

    // zero-pad phantom strip (both buffers)
    if (s == 0) {
#pragma unroll
        for (int j = 0; j < 3; j++) {
            bm0[0][j][c] = 0.0f;
            bm1[0][j][c] = 0.0f;
        }
    }

    // per-channel constants; fold r into the conv weights
    const float rr = __ldg(&r[cg]);
    const float ee = __ldg(&eps[cg]);
    const float bb = __ldg(&beta[cg]);
    const float k0 = __ldg(&Kc[cg * 4 + 0]);
    const float k1 = __ldg(&Kc[cg * 4 + 1]);
    const float k2 = __ldg(&Kc[cg * 4 + 2]);
    const float k3 = __ldg(&Kc[cg * 4 + 3]);
    const float onemb = 1.0f - bb;
    const float A  = onemb * (1.0f - ee);
    const float Bc = onemb * ee;
    const float v3 = fmaf(Bc, k3, A) * rr;   // coeff of m'[t]
    const float v2 = Bc * k2 * rr;           // m'[t-1]
    const float v1 = Bc * k1 * rr;           // m'[t-2]
    const float v0 = Bc * k0 * rr;           // m'[t-3]

    // load drive -> g init, D = beta * drive (step-invariant, in regs)
    float g[LL], D[LL];
#pragma unroll
    for (int i = 0; i < LL; i++) {
        const int gt = gt0 + s * LL + i;
        float d = 0.0f;
        if (gt >= 0 && gt < Tdim)
            d = drive[base + gt * Cdim + cg];
        g[i] = d;
        D[i] = bb * d;
    }

    // one fused step against a fixed exchange buffer (compile-time address)
#define CML_STEP(BUF)                                                        \
    {                                                                        \
        const float gA = g[LL - 3], gB = g[LL - 2], gC = g[LL - 1];          \
        const float tA = fmaf(-gA, gA, gA);                                  \
        const float tB = fmaf(-gB, gB, gB);                                  \
        const float tC = fmaf(-gC, gC, gC);                                  \
        BUF[s + 1][0][c] = tA;                                               \
        BUF[s + 1][1][c] = tB;                                               \
        BUF[s + 1][2][c] = tC;                                               \
        __syncthreads();                                                     \
        float m3 = BUF[s][0][c];                                             \
        float m2 = BUF[s][1][c];                                             \
        float m1 = BUF[s][2][c];                                             \
        _Pragma("unroll")                                                    \
        for (int i = 0; i < LL; i++) {                                       \
            const float gi = g[i];                                           \
            const float m0 = (i < LL - 3) ? fmaf(-gi, gi, gi)                \
                           : (i == LL - 3 ? tA : (i == LL - 2 ? tB : tC));   \
            float acc = fmaf(v3, m0, D[i]);                                  \
            acc = fmaf(v2, m1, acc);                                         \
            acc = fmaf(v1, m2, acc);                                         \
            g[i] = fmaf(v0, m3, acc);                                        \
            m3 = m2; m2 = m1; m1 = m0;                                       \
        }                                                                    \
    }

#pragma unroll 1
    for (int step = 0; step < NSTEPS / 2; step++) {
        CML_STEP(bm0);
        CML_STEP(bm1);
    }
#undef CML_STEP

    // clip + store valid region
#pragma unroll
    for (int i = 0; i < LL; i++) {
        const int lt = s * LL + i;
        const int gt = gt0 + lt;
        if (lt >= HALO && gt < Tdim) {
            const float v = fminf(fmaxf(g[i], 1.0e-4f), 1.0f - 1.0e-4f);
            out[base + gt * Cdim + cg] = v;
        }
    }
}

extern "C" void kernel_launch(void* const* d_in, const int* in_sizes, int n_in,
                              void* d_out, int out_size)
{
    const float* drive = (const float*)d_in[0];
    const float* r     = (const float*)d_in[1];
    const float* eps   = (const float*)d_in[2];
    const float* beta  = (const float*)d_in[3];
    const float* Kc    = (const float*)d_in[4];
    float* out = (float*)d_out;

    dim3 grid(NTILES, Cdim / CC, Bdim);   // 8 x 64 x 4 = 2048 CTAs
    cml_kernel<<<grid, CC * SS>>>(drive, r, eps, beta, Kc, out);
}

// round 17
// speedup vs baseline: 1.1834x; 1.1834x over previous
#include <cuda_runtime.h>
#include <cuda_bf16.h>

// CausalSequenceCML: 16 fused steps of depthwise-causal-conv logistic CML.
// B=4, T=4096, C=512, K=4, STEPS=16.
//
// FINAL (R15 verbatim, 43.4us = ~92% of the mixed-rt FFMA hardware floor).
// Converged design after 16 measured rounds:
//  - channel-per-thread, smem boundary exchange (only structure sustaining
//    ~51% fma = the FFMA-3reg rt=2 bank-limited ceiling)
//  - r folded into conv weights; m' = g*(1-g) = 1 dedup'd (rt=1) FMA;
//    5 FMA/cell-step total (algebraic floor for the 4-tap causal FIR)
//  - CC=8 x SS=40 x LL=14, 320 threads, occ 3. TILE=560, VALID=512,
//    NTILES=8: 8*512 = 4096 exact, amp=1.094 — enumerated geometry optimum
//  - tails reused across exchange+sweep; phantom zero strip (no branch);
//    one __syncthreads per step (proven hidden at occ 3)
// Falsified levers (do not revisit): f32x2 (R2), shfl exchange (R5/6/8),
// zero-halo (R7), smem D (R4), defer-block pipelining (R13), occ-2 wide
// blocks (R10), unroll-2 ping-pong (R16).

#define Bdim 4
#define Tdim 4096
#define Cdim 512
#define NSTEPS 16
#define CC 8                 // channels per block (thread c = tid&7)
#define SS 40                // time strips per block
#define LL 14                // cells per thread
#define TILE (SS * LL)       // 560
#define HALO 48              // 3 * NSTEPS
#define VALID (TILE - HALO)  // 512
#define NTILES (Tdim / VALID) // 8, exact

__global__ void __launch_bounds__(CC * SS, 3)
cml_kernel(const float* __restrict__ drive,
           const float* __restrict__ r,
           const float* __restrict__ eps,
           const float* __restrict__ beta,
           const float* __restrict__ Kc,
           float* __restrict__ out)
{
    // boundary m' values, phantom zero strip at index 0: [buf][strip+1][3][ch]
    __shared__ float bm[2][SS + 1][3][CC];

    const int tid = threadIdx.x;
    const int c   = tid & (CC - 1);
    const int s   = tid / CC;
    const int cg  = blockIdx.y * CC + c;
    const int b   = blockIdx.z;
    const int gt0 = (int)blockIdx.x * VALID - HALO;
    const int base = b * (Tdim * Cdim);

    // zero-pad phantom strip (both buffers)
    if (s == 0) {
#pragma unroll
        for (int j = 0; j < 3; j++) {
            bm[0][0][j][c] = 0.0f;
            bm[1][0][j][c] = 0.0f;
        }
    }

    // per-channel constants; fold r into the conv weights
    const float rr = r[cg];
    const float ee = eps[cg];
    const float bb = beta[cg];
    const float k0 = Kc[cg * 4 + 0];
    const float k1 = Kc[cg * 4 + 1];
    const float k2 = Kc[cg * 4 + 2];
    const float k3 = Kc[cg * 4 + 3];
    const float onemb = 1.0f - bb;
    const float A  = onemb * (1.0f - ee);
    const float Bc = onemb * ee;
    const float v3 = fmaf(Bc, k3, A) * rr;   // coeff of m'[t]
    const float v2 = Bc * k2 * rr;           // m'[t-1]
    const float v1 = Bc * k1 * rr;           // m'[t-2]
    const float v0 = Bc * k0 * rr;           // m'[t-3]

    // load drive -> g init, D = beta * drive (step-invariant, in regs)
    float g[LL], D[LL];
#pragma unroll
    for (int i = 0; i < LL; i++) {
        const int gt = gt0 + s * LL + i;
        float d = 0.0f;
        if (gt >= 0 && gt < Tdim)
            d = drive[base + gt * Cdim + cg];
        g[i] = d;
        D[i] = bb * d;
    }

#pragma unroll 1
    for (int step = 0; step < NSTEPS; step++) {
        float (*buf)[3][CC] = bm[step & 1];
        // boundary: m' of this strip's last 3 cells -> slot s+1 (kept live
        // and reused below for the sweep's last 3 cells)
        const float gA = g[LL - 3], gB = g[LL - 2], gC = g[LL - 1];
        const float tA = fmaf(-gA, gA, gA);
        const float tB = fmaf(-gB, gB, gB);
        const float tC = fmaf(-gC, gC, gC);
        buf[s + 1][0][c] = tA;
        buf[s + 1][1][c] = tB;
        buf[s + 1][2][c] = tC;
        __syncthreads();

        float m3 = buf[s][0][c];
        float m2 = buf[s][1][c];
        float m1 = buf[s][2][c];
        // main sweep: 5 FMA/cell; last-3 m' reused (compile-time select)
#pragma unroll
        for (int i = 0; i < LL; i++) {
            const float gi = g[i];
            const float m0 = (i < LL - 3) ? fmaf(-gi, gi, gi)
                           : (i == LL - 3 ? tA : (i == LL - 2 ? tB : tC));
            float acc = fmaf(v3, m0, D[i]);
            acc = fmaf(v2, m1, acc);
            acc = fmaf(v1, m2, acc);
            g[i] = fmaf(v0, m3, acc);
            m3 = m2; m2 = m1; m1 = m0;
        }
    }

    // clip + store valid region
#pragma unroll
    for (int i = 0; i < LL; i++) {
        const int lt = s * LL + i;
        const int gt = gt0 + lt;
        if (lt >= HALO && gt < Tdim) {
            const float v = fminf(fmaxf(g[i], 1.0e-4f), 1.0f - 1.0e-4f);
            out[base + gt * Cdim + cg] = v;
        }
    }
}

extern "C" void kernel_launch(void* const* d_in, const int* in_sizes, int n_in,
                              void* d_out, int out_size)
{
    const float* drive = (const float*)d_in[0];
    const float* r     = (const float*)d_in[1];
    const float* eps   = (const float*)d_in[2];
    const float* beta  = (const float*)d_in[3];
    const float* Kc    = (const float*)d_in[4];
    float* out = (float*)d_out;

    dim3 grid(NTILES, Cdim / CC, Bdim);   // 8 x 64 x 4 = 2048 CTAs
    cml_kernel<<<grid, CC * SS>>>(drive, r, eps, beta, Kc, out);
}